// round 11
// baseline (speedup 1.0000x reference)
#include <cuda_runtime.h>
#include <cuda_fp16.h>
#include <cstdint>
#include <cstddef>

#define T_STEPS 8192
#define F_DIM   1024
#define H_DIM   2048
#define G_DIM   (4 * H_DIM)
#define MAXB    256
#define NB      128            // persistent CTAs: 16 hidden units / 64 gate rows each
#define POISON  0x7E7E7E7Eu    // fp16 NaN pair; h = sig*tanh is finite -> never matches

// ---------------------------------------------------------------------------
// Static device scratch (no cudaMalloc anywhere)
// ---------------------------------------------------------------------------
__device__ float                    g_XG[(size_t)T_STEPS * G_DIM];   // x-gates, 256 MB
__device__ __half                   g_Whf[(size_t)G_DIM * H_DIM];    // fp16 W_hh, 32 MB
__device__ __half                   g_Xh [(size_t)T_STEPS * F_DIM];  // fp16 input, 16 MB
__device__ __half                   g_Wih[(size_t)G_DIM * F_DIM];    // fp16 W_ih, 16 MB
__device__ __align__(16) __half     g_hr[4][H_DIM];                  // 4-slot h ring
__device__ float                    g_partial[(size_t)T_STEPS * MAXB];

// ---------------------------------------------------------------------------
// Helpers
// ---------------------------------------------------------------------------
__device__ __forceinline__ unsigned sptr(const void* p) {
    unsigned a;
    asm("{ .reg .u64 t; cvta.to.shared.u64 t, %1; cvt.u32.u64 %0, t; }"
        : "=r"(a) : "l"(p));
    return a;
}
__device__ __forceinline__ void cp16(unsigned s, const void* g) {
    asm volatile("cp.async.cg.shared.global [%0], [%1], 16;" :: "r"(s), "l"(g));
}
__device__ __forceinline__ __half2 u2h(unsigned x) {
    __half2 h; *reinterpret_cast<unsigned*>(&h) = x; return h;
}
__device__ __forceinline__ void mac4(uint4 w, uint4 h, __half2& acc) {
    acc = __hfma2(u2h(w.x), u2h(h.x), acc);
    acc = __hfma2(u2h(w.y), u2h(h.y), acc);
    acc = __hfma2(u2h(w.z), u2h(h.z), acc);
    acc = __hfma2(u2h(w.w), u2h(h.w), acc);
}
__device__ __forceinline__ float tanh_fast(float x) {
    float y; asm("tanh.approx.f32 %0, %1;" : "=f"(y) : "f"(x)); return y;
}
__device__ __forceinline__ float sig_fast(float x) {
    return 0.5f + 0.5f * tanh_fast(0.5f * x);
}
__device__ __forceinline__ uint32_t ldacq(const uint32_t* p) {
    uint32_t v;
    asm volatile("ld.acquire.gpu.global.u32 %0, [%1];" : "=r"(v) : "l"(p) : "memory");
    return v;
}

// ---------------------------------------------------------------------------
// Kernel 1: fp32 -> fp16 conversion (X, W_ih, W_hh)
// ---------------------------------------------------------------------------
__global__ void conv_f2h(const float* __restrict__ S, __half* __restrict__ D, int n4) {
    int i = blockIdx.x * blockDim.x + threadIdx.x;
    if (i >= n4) return;
    float4 v = reinterpret_cast<const float4*>(S)[i];
    __half2* o = reinterpret_cast<__half2*>(D);
    o[i * 2 + 0] = __floats2half2_rn(v.x, v.y);
    o[i * 2 + 1] = __floats2half2_rn(v.z, v.w);
}

// ---------------------------------------------------------------------------
// Kernel 2: XG = X @ W_ih^T + b  via HMMA m16n8k16 (fp16 in, fp32 accum)
// ---------------------------------------------------------------------------
__global__ __launch_bounds__(256, 2) void gemm_xg_h(
    const float* __restrict__ bi, const float* __restrict__ bh)
{
    __shared__ __align__(16) __half As[2][128][40];
    __shared__ __align__(16) __half Ws[2][128][40];

    const int tid  = threadIdx.x;
    const int lane = tid & 31;
    const int wid  = tid >> 5;
    const int wm   = wid >> 2;
    const int wn   = wid & 3;
    const int bm   = blockIdx.y * 128;
    const int bn   = blockIdx.x * 128;
    const int fg   = lane >> 2;
    const int kq   = lane & 3;

    float c[4][4][4];
#pragma unroll
    for (int a = 0; a < 4; a++)
#pragma unroll
        for (int b = 0; b < 4; b++)
#pragma unroll
            for (int d = 0; d < 4; d++) c[a][b][d] = 0.f;

    float2 bias2[4];
#pragma unroll
    for (int nb = 0; nb < 4; nb++) {
        int col = bn + wn * 32 + nb * 8 + kq * 2;
        bias2[nb] = make_float2(bi[col] + bh[col], bi[col + 1] + bh[col + 1]);
    }

    const int lrow = tid >> 1, lq = tid & 1;
    const __half* gA = g_Xh  + (size_t)(bm + lrow) * F_DIM + lq * 16;
    const __half* gW = g_Wih + (size_t)(bn + lrow) * F_DIM + lq * 16;

    auto load_buf = [&](int buf, int k0) {
        unsigned da = sptr(&As[buf][lrow][lq * 16]);
        unsigned dw = sptr(&Ws[buf][lrow][lq * 16]);
        cp16(da,      gA + k0);
        cp16(da + 16, gA + k0 + 8);
        cp16(dw,      gW + k0);
        cp16(dw + 16, gW + k0 + 8);
    };

    load_buf(0, 0);
    asm volatile("cp.async.commit_group;" ::: "memory");
    asm volatile("cp.async.wait_group 0;" ::: "memory");
    __syncthreads();

    int buf = 0;
    for (int kt = 0; kt < F_DIM / 32; kt++) {
        if (kt + 1 < F_DIM / 32) {
            load_buf(buf ^ 1, (kt + 1) * 32);
            asm volatile("cp.async.commit_group;" ::: "memory");
        }
#pragma unroll
        for (int ks = 0; ks < 32; ks += 16) {
            unsigned bf[4][2];
#pragma unroll
            for (int nb = 0; nb < 4; nb++) {
                const __half* wp = &Ws[buf][wn * 32 + nb * 8 + fg][ks + kq * 2];
                bf[nb][0] = *reinterpret_cast<const unsigned*>(wp);
                bf[nb][1] = *reinterpret_cast<const unsigned*>(wp + 8);
            }
#pragma unroll
            for (int mb = 0; mb < 4; mb++) {
                const __half* ap = &As[buf][wm * 64 + mb * 16 + fg][ks + kq * 2];
                unsigned a0 = *reinterpret_cast<const unsigned*>(ap);
                unsigned a1 = *reinterpret_cast<const unsigned*>(ap + 8 * 40);
                unsigned a2 = *reinterpret_cast<const unsigned*>(ap + 8);
                unsigned a3 = *reinterpret_cast<const unsigned*>(ap + 8 * 40 + 8);
#pragma unroll
                for (int nb = 0; nb < 4; nb++) {
                    asm volatile(
                        "mma.sync.aligned.m16n8k16.row.col.f32.f16.f16.f32 "
                        "{%0,%1,%2,%3}, {%4,%5,%6,%7}, {%8,%9}, {%0,%1,%2,%3};"
                        : "+f"(c[mb][nb][0]), "+f"(c[mb][nb][1]),
                          "+f"(c[mb][nb][2]), "+f"(c[mb][nb][3])
                        : "r"(a0), "r"(a1), "r"(a2), "r"(a3),
                          "r"(bf[nb][0]), "r"(bf[nb][1]));
                }
            }
        }
        if (kt + 1 < F_DIM / 32)
            asm volatile("cp.async.wait_group 0;" ::: "memory");
        __syncthreads();
        buf ^= 1;
    }

#pragma unroll
    for (int mb = 0; mb < 4; mb++) {
        int row = bm + wm * 64 + mb * 16 + fg;
#pragma unroll
        for (int nb = 0; nb < 4; nb++) {
            int col = bn + wn * 32 + nb * 8 + kq * 2;
            float2 v0 = make_float2(c[mb][nb][0] + bias2[nb].x,
                                    c[mb][nb][1] + bias2[nb].y);
            float2 v1 = make_float2(c[mb][nb][2] + bias2[nb].x,
                                    c[mb][nb][3] + bias2[nb].y);
            *reinterpret_cast<float2*>(g_XG + (size_t)row * G_DIM + col)       = v0;
            *reinterpret_cast<float2*>(g_XG + (size_t)(row + 8) * G_DIM + col) = v1;
        }
    }
}

// ---------------------------------------------------------------------------
// Kernel 3: persistent HFMA2 LSTM recurrence, sentinel h-ring sync.
// Thread (w,l): row = 8w + (l>>2), K-segment = l&3 (512 k each).
// Per step: poll own 16B of h(t-1) until != POISON (this IS the sync),
// compute, warp0 poisons slot (t+1)%4 then release-writes h(t) to slot t%4.
// ---------------------------------------------------------------------------
__global__ __launch_bounds__(256, 1) void lstm_kernel(
    const float* __restrict__ Wout)
{
    extern __shared__ uint4 wsmT[];       // 32 x 256 uint4 = 128 KB, lane-transposed
    __shared__ uint4  h_sm4[4 * 65];      // h segments, stride 65 (conflict-free)
    __shared__ float  gates_sm[64];
    __shared__ float  xg_sm[2][64];

    const int tid  = threadIdx.x;
    const int lane = tid & 31;
    const int wid  = tid >> 5;
    const int b    = blockIdx.x;
    const int base = b * 16;

    const int row = wid * 8 + (lane >> 2);
    const int seg = lane & 3;

    auto growm = [&](int m) -> size_t {
        return (size_t)(m >> 4) * H_DIM + base + (m & 15);
    };

    const uint4* wp = reinterpret_cast<const uint4*>(
        g_Whf + growm(row) * H_DIM + seg * 512);

    uint4 wreg[32];
#pragma unroll
    for (int i = 0; i < 32; i++) wreg[i] = __ldg(wp + i);
    for (int i = 0; i < 32; i++) wsmT[i * 256 + tid] = __ldg(wp + 32 + i);

    float creg = 0.f;
    const float wout = (wid == 0 && lane < 16) ? Wout[base + lane] : 0.f;

    if (wid < 2) {
        int m = wid * 32 + lane;
        xg_sm[0][m] = __ldg(g_XG + growm(m));
    }
    __syncthreads();

    for (int t = 0; t < T_STEPS; t++) {
        const int rs = (t + 3) & 3;       // read slot: h(t-1)
        const int ws = t & 3;             // write slot: h(t)
        const int ps = (t + 1) & 3;       // poison slot (ahead)

        // ---- poll own 16B of h(t-1): the poll IS the sync + the load ----
        {
            const uint32_t* hw = reinterpret_cast<const uint32_t*>(g_hr[rs]) + tid * 4;
            uint4 hv;
            for (;;) {
                hv.x = ldacq(hw);
                hv.y = ldacq(hw + 1);
                hv.z = ldacq(hw + 2);
                hv.w = ldacq(hw + 3);
                if (hv.x != POISON && hv.y != POISON &&
                    hv.z != POISON && hv.w != POISON) break;
            }
            h_sm4[(tid >> 6) * 65 + (tid & 63)] = hv;
        }
        __syncthreads();

        // ---- per-thread dot over its 512-k segment ----
        const uint4* hA = &h_sm4[seg * 65];
        const uint4* hB = &h_sm4[seg * 65 + 32];
        float dot = 0.f;
        __half2 acc = __half2half2(__ushort_as_half(0));
#pragma unroll
        for (int i = 0; i < 32; i += 2) {
            mac4(wreg[i],     hA[i],     acc);
            mac4(wreg[i + 1], hA[i + 1], acc);
            float2 f = __half22float2(acc);
            dot += f.x + f.y;
            acc = __half2half2(__ushort_as_half(0));
        }
#pragma unroll
        for (int i = 0; i < 32; i += 2) {
            mac4(wsmT[i * 256 + tid],       hB[i],     acc);
            mac4(wsmT[(i + 1) * 256 + tid], hB[i + 1], acc);
            float2 f = __half22float2(acc);
            dot += f.x + f.y;
            acc = __half2half2(__ushort_as_half(0));
        }

        // ---- quad reduction ----
        dot += __shfl_xor_sync(0xffffffffu, dot, 1);
        dot += __shfl_xor_sync(0xffffffffu, dot, 2);
        if (seg == 0) gates_sm[row] = dot;
        __syncthreads();

        // ---- activations (warp 0) + poison-then-release h publish ----
        if (wid == 0) {
            float hn = 0.f;
            if (lane < 16) {
                float iv = gates_sm[lane]      + xg_sm[t & 1][lane];
                float fv = gates_sm[16 + lane] + xg_sm[t & 1][16 + lane];
                float gv = gates_sm[32 + lane] + xg_sm[t & 1][32 + lane];
                float ov = gates_sm[48 + lane] + xg_sm[t & 1][48 + lane];
                float cn = sig_fast(fv) * creg + sig_fast(iv) * tanh_fast(gv);
                hn = sig_fast(ov) * tanh_fast(cn);
                creg = cn;
            }
            float hpart = __shfl_xor_sync(0xffffffffu, hn, 1);
            if (lane < 16 && (lane & 1) == 0) {
                __half2 hp = __floats2half2_rn(hn, hpart);
                uint32_t pk = *reinterpret_cast<uint32_t*>(&hp);
                uint32_t* wsl = reinterpret_cast<uint32_t*>(g_hr[ws]) + (base >> 1) + (lane >> 1);
                uint32_t* psl = reinterpret_cast<uint32_t*>(g_hr[ps]) + (base >> 1) + (lane >> 1);
                *psl = POISON;   // plain store; ordered before release below
                asm volatile("st.release.gpu.global.u32 [%0], %1;"
                             :: "l"(wsl), "r"(pk) : "memory");
            }
            // shadow: output partial
            float pv = hn * wout;
#pragma unroll
            for (int o = 16; o; o >>= 1) pv += __shfl_xor_sync(0xffffffffu, pv, o);
            if (lane == 0) g_partial[(size_t)t * MAXB + b] = pv;
        }

        // shadow: xg prefetch into the other buffer (warps 1,2)
        if ((wid == 1 || wid == 2) && t + 1 < T_STEPS) {
            int m = (wid - 1) * 32 + lane;
            xg_sm[(t + 1) & 1][m] = __ldg(g_XG + (size_t)(t + 1) * G_DIM + growm(m));
        }
        // no central barrier: next iteration's poll provides the sync
    }
}

// ---------------------------------------------------------------------------
// Kernel 4: out[t] = b_out + sum_b partial[t][b]  (fixed order, deterministic)
// ---------------------------------------------------------------------------
__global__ void reduce_out(const float* __restrict__ bo, float* __restrict__ out) {
    int t = blockIdx.x * blockDim.x + threadIdx.x;
    if (t >= T_STEPS) return;
    float s = bo[0];
    const float* p = g_partial + (size_t)t * MAXB;
    for (int b = 0; b < NB; b++) s += p[b];
    out[t] = s;
}

// ---------------------------------------------------------------------------
// Host launcher (graph-capturable: kernels + async memsets only)
// ---------------------------------------------------------------------------
extern "C" void kernel_launch(void* const* d_in, const int* in_sizes, int n_in,
                              void* d_out, int out_size)
{
    const float* input = (const float*)d_in[0];   // [T, 1, F]
    const float* W_ih  = (const float*)d_in[1];   // [4H, F]
    const float* W_hh  = (const float*)d_in[2];   // [4H, H]
    const float* b_ih  = (const float*)d_in[3];
    const float* b_hh  = (const float*)d_in[4];
    const float* W_out = (const float*)d_in[5];   // [1, H]
    const float* b_out = (const float*)d_in[6];
    float* out = (float*)d_out;                   // [T, 1, 1]

    const size_t smem = (size_t)32 * 256 * sizeof(uint4);   // 131072 B
    cudaFuncSetAttribute(lstm_kernel, cudaFuncAttributeMaxDynamicSharedMemorySize,
                         (int)smem);

    // h ring init: slots 0-2 = POISON bytes, slot 3 = zeros (h(-1) = 0)
    char* hrp = nullptr; cudaGetSymbolAddress((void**)&hrp, g_hr);
    cudaMemsetAsync(hrp, 0x7E, 4 * H_DIM * sizeof(__half));
    cudaMemsetAsync(hrp + 3 * H_DIM * sizeof(__half), 0, H_DIM * sizeof(__half));

    __half* xh = nullptr;  cudaGetSymbolAddress((void**)&xh,  g_Xh);
    __half* wih = nullptr; cudaGetSymbolAddress((void**)&wih, g_Wih);
    __half* whf = nullptr; cudaGetSymbolAddress((void**)&whf, g_Whf);

    conv_f2h<<<(T_STEPS * F_DIM / 4 + 255) / 256, 256>>>(input, xh,
                                                         T_STEPS * F_DIM / 4);
    conv_f2h<<<(G_DIM * F_DIM / 4 + 255) / 256, 256>>>(W_ih, wih,
                                                       G_DIM * F_DIM / 4);
    conv_f2h<<<(G_DIM * H_DIM / 4 + 255) / 256, 256>>>(W_hh, whf,
                                                       G_DIM * H_DIM / 4);

    dim3 ggrid(G_DIM / 128, T_STEPS / 128);
    gemm_xg_h<<<ggrid, 256>>>(b_ih, b_hh);

    lstm_kernel<<<NB, 256, smem>>>(W_out);

    reduce_out<<<(T_STEPS + 255) / 256, 256>>>(b_out, out);
}